// round 10
// baseline (speedup 1.0000x reference)
#include <cuda_runtime.h>
#include <cuda_bf16.h>
#include <cstdint>
#include <cstddef>

// ============================================================================
// TT-Linear as two merged GEMMs on HMMA (mma.sync bf16, baseline compute_103).
//
//   stage1: z[b][m=512][i34] = G01(512x64) @ x_b^T          (K=64)
//   stage2: y[(b,o12)][o34]  = z_rows @ G23(512x64) + bias  (K=512)
//   3-term bf16 split per GEMM: Ah*Bh + Ah*Bl + Al*Bh.
//
// Fragment-order operands (hi/lo planes separated): every fragment is one
// LDS.128, zero PRMT on the B/A-stationary paths. MMAs issued term-major.
// R9 fix: g_XT writer index had [b&3] and [ks] dims transposed vs the k1
// reader ([ks]-major over the 256-col chunk). Corrected to
//   ks*4096 + (b&3)*1024 + nb_rel*128 + lane*4 + w.
// ============================================================================

// fragment-order layouts:
//  g_A : [mrb=32][ks=4][lane=32][8 words: a0h,a1h,a2h,a3h,a0l,a1l,a2l,a3l]
//  g_B : [ks=32][nb=8][lane=32][4 words: b0h,b1h,b0l,b1l]
//  g_XT: [nc=1024][ks=4][nb=32][lane=32][4 words: b0h,b1h,b0l,b1l]
__device__ __align__(16) uint32_t g_A[32768];
__device__ __align__(16) uint32_t g_B[32768];
__device__ __align__(16) uint32_t g_XT[1024u * 16384u];
__device__ __align__(16) uint32_t g_Z[134217728u];   // z {h,l} words [b][m][i34]

// ---------------------------------------------------------------- helpers
__device__ __forceinline__ uint32_t prmt(uint32_t a, uint32_t b, uint32_t s) {
    uint32_t d;
    asm("prmt.b32 %0, %1, %2, %3;" : "=r"(d) : "r"(a), "r"(b), "r"(s));
    return d;
}
__device__ __forceinline__ uint32_t pack_hl(float f) {
    __nv_bfloat16 h = __float2bfloat16(f);
    float hf = __bfloat162float(h);
    __nv_bfloat16 l = __float2bfloat16(f - hf);
    return (uint32_t)__bfloat16_as_ushort(h) |
           ((uint32_t)__bfloat16_as_ushort(l) << 16);
}
// pack plane word from two floats: plane 0 = hi pair, plane 1 = lo pair
__device__ __forceinline__ uint32_t pack_plane(float a, float b, int plane) {
    __nv_bfloat16 ha = __float2bfloat16(a), hb = __float2bfloat16(b);
    if (plane == 0)
        return (uint32_t)__bfloat16_as_ushort(ha) |
               ((uint32_t)__bfloat16_as_ushort(hb) << 16);
    __nv_bfloat16 la = __float2bfloat16(a - __bfloat162float(ha));
    __nv_bfloat16 lb = __float2bfloat16(b - __bfloat162float(hb));
    return (uint32_t)__bfloat16_as_ushort(la) |
           ((uint32_t)__bfloat16_as_ushort(lb) << 16);
}
#define SPLIT_HL(w, H, L) do { H = prmt((w).x, (w).y, 0x5410); \
                               L = prmt((w).x, (w).y, 0x7632); } while (0)

__device__ __forceinline__ void mma16816(float* c, const uint32_t* a,
                                         const uint32_t* b) {
    asm volatile(
        "mma.sync.aligned.m16n8k16.row.col.f32.bf16.bf16.f32 "
        "{%0,%1,%2,%3}, {%4,%5,%6,%7}, {%8,%9}, {%0,%1,%2,%3};"
        : "+f"(c[0]), "+f"(c[1]), "+f"(c[2]), "+f"(c[3])
        : "r"(a[0]), "r"(a[1]), "r"(a[2]), "r"(a[3]), "r"(b[0]), "r"(b[1]));
}
__device__ __forceinline__ void cpa16(uint32_t dst_smem, const void* src) {
    asm volatile("cp.async.cg.shared.global [%0], [%1], 16;"
                 :: "r"(dst_smem), "l"(src) : "memory");
}
__device__ __forceinline__ void cpa_commit() {
    asm volatile("cp.async.commit_group;" ::: "memory");
}
__device__ __forceinline__ void cpa_wait0() {
    asm volatile("cp.async.wait_group 0;" ::: "memory");
}
__device__ __forceinline__ void cpa_wait1() {
    asm volatile("cp.async.wait_group 1;" ::: "memory");
}

// ---------------------------------------------------------------------------
// prep: merge core pairs straight into fragment-order hi/lo planes.
// ---------------------------------------------------------------------------
__global__ void k_prep(const float* __restrict__ c0, const float* __restrict__ c1,
                       const float* __restrict__ c2, const float* __restrict__ c3) {
    int t = blockIdx.x * blockDim.x + threadIdx.x;  // 0..65535
    if (t < 32768) {
        // g_A word t: [mrb][ks][lane][w]; w: plane = w>>2, w2 = w&3
        int w = t & 7, lane = (t >> 3) & 31, ks = (t >> 8) & 3, mrb = t >> 10;
        int g = lane >> 2, t4 = lane & 3;
        int w2 = w & 3, plane = w >> 2;
        int m  = mrb * 16 + (w2 & 1) * 8 + g;
        int k0 = ks * 16 + ((w2 >> 1) & 1) * 8 + t4 * 2;
        int o1 = m >> 6, o2 = (m >> 3) & 7, r2 = m & 7;
        float s[2];
#pragma unroll
        for (int d = 0; d < 2; ++d) {
            int k = k0 + d;
            int i1 = k >> 3, i2 = k & 7;
            float acc = 0.0f;
#pragma unroll
            for (int r1 = 0; r1 < 8; ++r1)
                acc += c0[(i1 * 8 + o1) * 8 + r1] *
                       c1[((r1 * 8 + i2) * 8 + o2) * 8 + r2];
            s[d] = acc;
        }
        g_A[t] = pack_plane(s[0], s[1], plane);
    } else {
        // g_B word u: [ks][nb][lane][w]; w: k_half = w&1, plane = w>>1
        int u = t - 32768;
        int w = u & 3, lane = (u >> 2) & 31, nb = (u >> 7) & 7, ks = u >> 10;
        int g = lane >> 2, t4 = lane & 3;
        int plane = w >> 1;
        int n  = nb * 8 + g;
        int k0 = ks * 16 + (w & 1) * 8 + t4 * 2;
        int o3 = n >> 3, o4 = n & 7;
        float s[2];
#pragma unroll
        for (int d = 0; d < 2; ++d) {
            int k2 = k0 + d;
            int r2 = k2 >> 6, i3 = (k2 >> 3) & 7, i4 = k2 & 7;
            float acc = 0.0f;
#pragma unroll
            for (int r3 = 0; r3 < 8; ++r3)
                acc += c2[((r2 * 8 + i3) * 8 + o3) * 8 + r3] *
                       c3[(r3 * 8 + i4) * 8 + o4];
            s[d] = acc;
        }
        g_B[u] = pack_plane(s[0], s[1], plane);
    }
}

// ---------------------------------------------------------------------------
// splitXT: x[b] fp32 -> fragment-order hi/lo plane words in g_XT.
// One CTA per batch row. Chunk nc = b>>2 holds 4 batch rows, ks-major:
//   word index within chunk = ks*4096 + (b&3)*1024 + nb_rel*128 + lane*4 + w
// (matches k1's reader: [ks=4][nb=32][lane=32][w=4], nb = (b&3)*8 + nb_rel).
// ---------------------------------------------------------------------------
__global__ __launch_bounds__(256) void k_splitXT(const float* __restrict__ x) {
    __shared__ float sx[64 * 65];   // [i12][i34], pad 65
    const int tid = threadIdx.x;
    const int b = blockIdx.x;
    const float4* src = (const float4*)(x + (size_t)b * 4096);
#pragma unroll
    for (int p = 0; p < 4; ++p) {
        float4 v = src[tid + 256 * p];
        int j = tid + 256 * p;
        int i12 = j >> 4, c = (j & 15) * 4;
        float* d = &sx[i12 * 65 + c];
        d[0] = v.x; d[1] = v.y; d[2] = v.z; d[3] = v.w;
    }
    __syncthreads();
    uint32_t* chunk = g_XT + (size_t)(b >> 2) * 16384u;
    const int brel = b & 3;
#pragma unroll
    for (int it = 0; it < 16; ++it) {
        int widx = it * 256 + tid;  // [ks=4][nb_rel=8][lane=32][w=4]
        int w = widx & 3, lane = (widx >> 2) & 31;
        int nb_rel = (widx >> 7) & 7, ks = widx >> 10;
        int g = lane >> 2, t4 = lane & 3;
        int plane = w >> 1;
        int i34 = nb_rel * 8 + g;
        int k0 = ks * 16 + (w & 1) * 8 + t4 * 2;
        float f0 = sx[k0 * 65 + i34];
        float f1 = sx[(k0 + 1) * 65 + i34];
        // FIXED index: ks-major over chunk, batch row inside
        chunk[ks * 4096 + brel * 1024 + nb_rel * 128 + lane * 4 + w] =
            pack_plane(f0, f1, plane);
    }
}

// ---------------------------------------------------------------------------
// k1 (stage 1): z = G01 @ X^T.  512 thr / 16 warps, CTA tile 128m x 256n.
// Warp grid 2m x 8n, warp tile 64m x 32n.  All fragments via LDS.128.
// SMEM: sA 32KB + double-buffered sB 2x64KB = 160KB.
// ---------------------------------------------------------------------------
__global__ __launch_bounds__(512, 1) void k1() {
    extern __shared__ uint32_t sm1[];
    uint32_t* sA = sm1;                        // 8192 words
    const int tid = threadIdx.x;
    const int lane = tid & 31, w = tid >> 5;
    const int g = lane >> 2, t4 = lane & 3;
    const int wm = w & 1, wn = w >> 1;         // 2 x 8 warp grid
    const int mc = blockIdx.x & 3;
    const int nc0 = blockIdx.x >> 2;           // 0..147

    // stationary A chunk (fragment-order, verbatim copy)
    {
        const uint4* srcA = (const uint4*)(g_A + mc * 8192);
        for (int j = tid; j < 2048; j += 512)
            ((uint4*)sA)[j] = srcA[j];
    }
    // prologue: first B chunk into buffer 0 (verbatim bulk copy)
    {
        uint32_t* sB = sm1 + 8192;
        const uint4* src = (const uint4*)(g_XT + (size_t)nc0 * 16384u);
        for (int j = tid; j < 4096; j += 512)
            cpa16((uint32_t)__cvta_generic_to_shared(&sB[j * 4]), &src[j]);
        cpa_commit();
    }

    int it = 0;
    for (int nc = nc0; nc < 1024; nc += 148, ++it) {
        uint32_t* sB = sm1 + 8192 + (it & 1) * 16384;
        int ncn = nc + 148;
        if (ncn < 1024) {
            uint32_t* sBn = sm1 + 8192 + ((it + 1) & 1) * 16384;
            const uint4* src = (const uint4*)(g_XT + (size_t)ncn * 16384u);
            for (int j = tid; j < 4096; j += 512)
                cpa16((uint32_t)__cvta_generic_to_shared(&sBn[j * 4]), &src[j]);
            cpa_commit();
            cpa_wait1();
        } else {
            cpa_wait0();
        }
        __syncthreads();

        float acc[4][4][4];
#pragma unroll
        for (int a = 0; a < 4; ++a)
#pragma unroll
            for (int b = 0; b < 4; ++b)
#pragma unroll
                for (int q = 0; q < 4; ++q) acc[a][b][q] = 0.0f;

#pragma unroll
        for (int ks = 0; ks < 4; ++ks) {
            uint4 AH[4], AL[4], BQ[4];
#pragma unroll
            for (int mt = 0; mt < 4; ++mt) {
                int base = (((wm * 4 + mt) * 4 + ks) * 32 + lane) * 8;
                AH[mt] = *(const uint4*)&sA[base];
                AL[mt] = *(const uint4*)&sA[base + 4];
            }
#pragma unroll
            for (int nt = 0; nt < 4; ++nt)
                BQ[nt] = *(const uint4*)&sB[((ks * 32 + wn * 4 + nt) * 32 + lane) * 4];

            // term-major: hh (16), hl (16), lh (16) -> dep distance 16
#pragma unroll
            for (int mt = 0; mt < 4; ++mt)
#pragma unroll
                for (int nt = 0; nt < 4; ++nt)
                    mma16816(acc[mt][nt], (const uint32_t*)&AH[mt],
                             (const uint32_t*)&BQ[nt]);        // hh
#pragma unroll
            for (int mt = 0; mt < 4; ++mt)
#pragma unroll
                for (int nt = 0; nt < 4; ++nt)
                    mma16816(acc[mt][nt], (const uint32_t*)&AH[mt],
                             ((const uint32_t*)&BQ[nt]) + 2);  // hl
#pragma unroll
            for (int mt = 0; mt < 4; ++mt)
#pragma unroll
                for (int nt = 0; nt < 4; ++nt)
                    mma16816(acc[mt][nt], (const uint32_t*)&AL[mt],
                             (const uint32_t*)&BQ[nt]);        // lh
        }

        // store z tile: interleaved {h,l} words, STG.64
        const int b0 = nc * 4;
#pragma unroll
        for (int mt = 0; mt < 4; ++mt) {
            int row = mc * 128 + wm * 64 + mt * 16 + g;
#pragma unroll
            for (int nt = 0; nt < 4; ++nt) {
                int ncol = wn * 32 + nt * 8 + t4 * 2;
                int bl2 = ncol >> 6, i34 = ncol & 63;
                size_t base = ((size_t)(b0 + bl2) * 512 + row) * 64 + i34;
                uint2 v0, v1;
                v0.x = pack_hl(acc[mt][nt][0]);
                v0.y = pack_hl(acc[mt][nt][1]);
                v1.x = pack_hl(acc[mt][nt][2]);
                v1.y = pack_hl(acc[mt][nt][3]);
                *(uint2*)&g_Z[base] = v0;
                *(uint2*)&g_Z[base + 8 * 64] = v1;
            }
        }
        __syncthreads();
    }
}

// ---------------------------------------------------------------------------
// k2 (stage 2): y = Z @ G23 + bias. 512 thr / 16 warps, CTA = 512 rows.
// B fragment-order in SMEM (LDS.128, zero PRMT); Z streamed into A-frags
// via LDG.64 + PRMT with 1-deep k-prefetch. Term-major MMA in nt-halves.
// ---------------------------------------------------------------------------
__global__ __launch_bounds__(512, 1) void k2(const float* __restrict__ bias,
                                             float* __restrict__ out) {
    extern __shared__ uint32_t sm2[];   // 32768 words = 128KB
    uint32_t* sB = sm2;
    const int tid = threadIdx.x;
    const int lane = tid & 31, w = tid >> 5;
    const int g = lane >> 2, t4 = lane & 3;

    {
        const uint4* src = (const uint4*)g_B;
        for (int j = tid; j < 8192; j += 512)
            ((uint4*)sB)[j] = src[j];
    }

    const uint32_t* p0[2];
    const uint32_t* p8[2];
#pragma unroll
    for (int mt = 0; mt < 2; ++mt) {
        size_t gr = (size_t)blockIdx.x * 512 + w * 32 + mt * 16 + g;
        p0[mt] = g_Z + gr * 512;
        p8[mt] = g_Z + (gr + 8) * 512;
    }

    float acc[2][8][4];
#pragma unroll
    for (int a = 0; a < 2; ++a)
#pragma unroll
        for (int b = 0; b < 8; ++b)
#pragma unroll
            for (int q = 0; q < 4; ++q) acc[a][b][q] = 0.0f;

    uint2 aw[2][2][4];
    {
        const int kA = t4 * 2;
#pragma unroll
        for (int mt = 0; mt < 2; ++mt) {
            aw[0][mt][0] = *(const uint2*)(p0[mt] + kA);
            aw[0][mt][1] = *(const uint2*)(p8[mt] + kA);
            aw[0][mt][2] = *(const uint2*)(p0[mt] + kA + 8);
            aw[0][mt][3] = *(const uint2*)(p8[mt] + kA + 8);
        }
    }
    __syncthreads();

    for (int ks = 0; ks < 32; ++ks) {
        const int cur = ks & 1;
        if (ks < 31) {  // prefetch next k-step's A words
            const int kA = (ks + 1) * 16 + t4 * 2;
#pragma unroll
            for (int mt = 0; mt < 2; ++mt) {
                aw[cur ^ 1][mt][0] = *(const uint2*)(p0[mt] + kA);
                aw[cur ^ 1][mt][1] = *(const uint2*)(p8[mt] + kA);
                aw[cur ^ 1][mt][2] = *(const uint2*)(p0[mt] + kA + 8);
                aw[cur ^ 1][mt][3] = *(const uint2*)(p8[mt] + kA + 8);
            }
        }
        uint32_t ah[2][4], al[2][4];
#pragma unroll
        for (int mt = 0; mt < 2; ++mt) {
            SPLIT_HL(aw[cur][mt][0], ah[mt][0], al[mt][0]);
            SPLIT_HL(aw[cur][mt][1], ah[mt][1], al[mt][1]);
            SPLIT_HL(aw[cur][mt][2], ah[mt][2], al[mt][2]);
            SPLIT_HL(aw[cur][mt][3], ah[mt][3], al[mt][3]);
        }
#pragma unroll
        for (int half = 0; half < 2; ++half) {
            uint4 BQ[4];
#pragma unroll
            for (int j = 0; j < 4; ++j) {
                int nb = half * 4 + j;
                BQ[j] = *(const uint4*)&sB[((ks * 8 + nb) * 32 + lane) * 4];
            }
            // term-major within half: dep distance 8
#pragma unroll
            for (int j = 0; j < 4; ++j)
#pragma unroll
                for (int mt = 0; mt < 2; ++mt)
                    mma16816(acc[mt][half * 4 + j], ah[mt],
                             (const uint32_t*)&BQ[j]);        // hh
#pragma unroll
            for (int j = 0; j < 4; ++j)
#pragma unroll
                for (int mt = 0; mt < 2; ++mt)
                    mma16816(acc[mt][half * 4 + j], ah[mt],
                             ((const uint32_t*)&BQ[j]) + 2);  // hl
#pragma unroll
            for (int j = 0; j < 4; ++j)
#pragma unroll
                for (int mt = 0; mt < 2; ++mt)
                    mma16816(acc[mt][half * 4 + j], al[mt],
                             (const uint32_t*)&BQ[j]);        // lh
        }
    }

    // epilogue: +bias, store
#pragma unroll
    for (int mt = 0; mt < 2; ++mt) {
        size_t grow0 = (size_t)blockIdx.x * 512 + w * 32 + mt * 16 + g;
#pragma unroll
        for (int half = 0; half < 2; ++half) {
            size_t grow = grow0 + half * 8;
            int o12 = (int)(grow & 63);
            float* orow = out + grow * 64;
            const int ci = half * 2;
#pragma unroll
            for (int nt = 0; nt < 8; ++nt) {
                int col = nt * 8 + t4 * 2;
                float2 bv = __ldg((const float2*)&bias[o12 * 64 + col]);
                float2 v;
                v.x = acc[mt][nt][ci] + bv.x;
                v.y = acc[mt][nt][ci + 1] + bv.y;
                *(float2*)&orow[col] = v;
            }
        }
    }
}

// ---------------------------------------------------------------------------
extern "C" void kernel_launch(void* const* d_in, const int* in_sizes, int n_in,
                              void* d_out, int out_size) {
    (void)in_sizes; (void)n_in; (void)out_size;
    const float* x    = (const float*)d_in[0];
    const float* c0   = (const float*)d_in[1];
    const float* c1   = (const float*)d_in[2];
    const float* c2   = (const float*)d_in[3];
    const float* c3   = (const float*)d_in[4];
    const float* bias = (const float*)d_in[5];
    float* out = (float*)d_out;

    cudaFuncSetAttribute(k1, cudaFuncAttributeMaxDynamicSharedMemorySize, 163840);
    cudaFuncSetAttribute(k2, cudaFuncAttributeMaxDynamicSharedMemorySize, 131072);

    k_prep<<<256, 256>>>(c0, c1, c2, c3);
    k_splitXT<<<4096, 256>>>(x);
    k1<<<592, 512, 163840>>>();            // fragment-order operands, 0 PRMT
    k2<<<512, 512, 131072>>>(bias, out);   // frag-order B, term-major MMA
}

// round 11
// speedup vs baseline: 1.1208x; 1.1208x over previous
#include <cuda_runtime.h>
#include <cuda_bf16.h>
#include <cstdint>
#include <cstddef>

// ============================================================================
// TT-Linear as two merged GEMMs on HMMA (mma.sync bf16, baseline compute_103).
//
//   stage1: z[b][m=512][i34] = G01(512x64) @ x_b^T          (K=64)
//   stage2: y[(b,o12)][o34]  = z_rows @ G23(512x64) + bias  (K=512)
//   3-term bf16 split per GEMM: Ah*Bh + Ah*Bl + Al*Bh.
//
// R10 change: G01 rows relabeled m̂ = r2*64 + o12, so k1's accumulator quads
// ARE k2 A-fragment words. z stored as two plane arrays in k2-fragment order:
//   g_Z{h,l}[Rb=16384][ks=32][lane=32][4 words {a0,a1,a2,a3}]
// k1 epilogue: one coalesced STG.128 per plane per (mt,ntpair) (4 wf).
// k2 A-path: 4 coalesced LDG.128 per warp-ks (16 wf, zero PRMT).
// ============================================================================

// fragment-order layouts:
//  g_A : [mrb=32][ks=4][lane=32][8 words: a0h,a1h,a2h,a3h,a0l,a1l,a2l,a3l]
//        row m̂ = r2*64 + o12  (r2-major!)
//  g_B : [ks=32][nb=8][lane=32][4 words: b0h,b1h,b0l,b1l]
//  g_XT: [nc=1024][ks=4][nb=32][lane=32][4 words: b0h,b1h,b0l,b1l]
__device__ __align__(16) uint32_t g_A[32768];
__device__ __align__(16) uint32_t g_B[32768];
__device__ __align__(16) uint32_t g_XT[1024u * 16384u];
__device__ __align__(16) uint32_t g_Zh[67108864u];  // hi plane, fragment order
__device__ __align__(16) uint32_t g_Zl[67108864u];  // lo plane, fragment order

// ---------------------------------------------------------------- helpers
__device__ __forceinline__ uint32_t pack_plane(float a, float b, int plane) {
    __nv_bfloat16 ha = __float2bfloat16(a), hb = __float2bfloat16(b);
    if (plane == 0)
        return (uint32_t)__bfloat16_as_ushort(ha) |
               ((uint32_t)__bfloat16_as_ushort(hb) << 16);
    __nv_bfloat16 la = __float2bfloat16(a - __bfloat162float(ha));
    __nv_bfloat16 lb = __float2bfloat16(b - __bfloat162float(hb));
    return (uint32_t)__bfloat16_as_ushort(la) |
           ((uint32_t)__bfloat16_as_ushort(lb) << 16);
}

__device__ __forceinline__ void mma16816(float* c, const uint32_t* a,
                                         const uint32_t* b) {
    asm volatile(
        "mma.sync.aligned.m16n8k16.row.col.f32.bf16.bf16.f32 "
        "{%0,%1,%2,%3}, {%4,%5,%6,%7}, {%8,%9}, {%0,%1,%2,%3};"
        : "+f"(c[0]), "+f"(c[1]), "+f"(c[2]), "+f"(c[3])
        : "r"(a[0]), "r"(a[1]), "r"(a[2]), "r"(a[3]), "r"(b[0]), "r"(b[1]));
}
__device__ __forceinline__ void cpa16(uint32_t dst_smem, const void* src) {
    asm volatile("cp.async.cg.shared.global [%0], [%1], 16;"
                 :: "r"(dst_smem), "l"(src) : "memory");
}
__device__ __forceinline__ void cpa_commit() {
    asm volatile("cp.async.commit_group;" ::: "memory");
}
__device__ __forceinline__ void cpa_wait0() {
    asm volatile("cp.async.wait_group 0;" ::: "memory");
}
__device__ __forceinline__ void cpa_wait1() {
    asm volatile("cp.async.wait_group 1;" ::: "memory");
}

// ---------------------------------------------------------------------------
// prep: merge core pairs straight into fragment-order hi/lo planes.
// g_A uses the NEW row labeling m̂ = r2*64 + o12.
// ---------------------------------------------------------------------------
__global__ void k_prep(const float* __restrict__ c0, const float* __restrict__ c1,
                       const float* __restrict__ c2, const float* __restrict__ c3) {
    int t = blockIdx.x * blockDim.x + threadIdx.x;  // 0..65535
    if (t < 32768) {
        // g_A word t: [mrb][ks][lane][w]; w2 = w&3 (a-index), plane = w>>2
        int w = t & 7, lane = (t >> 3) & 31, ks = (t >> 8) & 3, mrb = t >> 10;
        int g = lane >> 2, t4 = lane & 3;
        int w2 = w & 3, plane = w >> 2;
        int mhat = mrb * 16 + (w2 & 1) * 8 + g;      // m̂ = r2*64 + o12
        int k0 = ks * 16 + ((w2 >> 1) & 1) * 8 + t4 * 2;
        int r2 = mhat >> 6, o12 = mhat & 63;
        int o1 = o12 >> 3, o2 = o12 & 7;
        float s[2];
#pragma unroll
        for (int d = 0; d < 2; ++d) {
            int k = k0 + d;
            int i1 = k >> 3, i2 = k & 7;
            float acc = 0.0f;
#pragma unroll
            for (int r1 = 0; r1 < 8; ++r1)
                acc += c0[(i1 * 8 + o1) * 8 + r1] *
                       c1[((r1 * 8 + i2) * 8 + o2) * 8 + r2];
            s[d] = acc;
        }
        g_A[t] = pack_plane(s[0], s[1], plane);
    } else {
        // g_B word u: [ks][nb][lane][w]; w: k_half = w&1, plane = w>>1
        int u = t - 32768;
        int w = u & 3, lane = (u >> 2) & 31, nb = (u >> 7) & 7, ks = u >> 10;
        int g = lane >> 2, t4 = lane & 3;
        int plane = w >> 1;
        int n  = nb * 8 + g;
        int k0 = ks * 16 + (w & 1) * 8 + t4 * 2;
        int o3 = n >> 3, o4 = n & 7;
        float s[2];
#pragma unroll
        for (int d = 0; d < 2; ++d) {
            int k2 = k0 + d;
            int r2 = k2 >> 6, i3 = (k2 >> 3) & 7, i4 = k2 & 7;
            float acc = 0.0f;
#pragma unroll
            for (int r3 = 0; r3 < 8; ++r3)
                acc += c2[((r2 * 8 + i3) * 8 + o3) * 8 + r3] *
                       c3[(r3 * 8 + i4) * 8 + o4];
            s[d] = acc;
        }
        g_B[u] = pack_plane(s[0], s[1], plane);
    }
}

// ---------------------------------------------------------------------------
// splitXT: x[b] fp32 -> fragment-order hi/lo plane words in g_XT.
// Chunk nc = b>>2, ks-major:  ks*4096 + (b&3)*1024 + nb_rel*128 + lane*4 + w.
// ---------------------------------------------------------------------------
__global__ __launch_bounds__(256) void k_splitXT(const float* __restrict__ x) {
    __shared__ float sx[64 * 65];   // [i12][i34], pad 65
    const int tid = threadIdx.x;
    const int b = blockIdx.x;
    const float4* src = (const float4*)(x + (size_t)b * 4096);
#pragma unroll
    for (int p = 0; p < 4; ++p) {
        float4 v = src[tid + 256 * p];
        int j = tid + 256 * p;
        int i12 = j >> 4, c = (j & 15) * 4;
        float* d = &sx[i12 * 65 + c];
        d[0] = v.x; d[1] = v.y; d[2] = v.z; d[3] = v.w;
    }
    __syncthreads();
    uint32_t* chunk = g_XT + (size_t)(b >> 2) * 16384u;
    const int brel = b & 3;
#pragma unroll
    for (int it = 0; it < 16; ++it) {
        int widx = it * 256 + tid;  // [ks=4][nb_rel=8][lane=32][w=4]
        int w = widx & 3, lane = (widx >> 2) & 31;
        int nb_rel = (widx >> 7) & 7, ks = widx >> 10;
        int g = lane >> 2, t4 = lane & 3;
        int plane = w >> 1;
        int i34 = nb_rel * 8 + g;
        int k0 = ks * 16 + (w & 1) * 8 + t4 * 2;
        float f0 = sx[k0 * 65 + i34];
        float f1 = sx[(k0 + 1) * 65 + i34];
        chunk[ks * 4096 + brel * 1024 + nb_rel * 128 + lane * 4 + w] =
            pack_plane(f0, f1, plane);
    }
}

// ---------------------------------------------------------------------------
// k1 (stage 1): z = G01 @ X^T.  512 thr / 16 warps, CTA tile 128m x 256n.
// Warp grid 2m x 8n, warp tile 64m x 32n.  All fragments via LDS.128.
// Epilogue: per (mt, ntpair) one coalesced STG.128 per plane into g_Z{h,l}.
// ---------------------------------------------------------------------------
__global__ __launch_bounds__(512, 1) void k1() {
    extern __shared__ uint32_t sm1[];
    uint32_t* sA = sm1;                        // 8192 words
    const int tid = threadIdx.x;
    const int lane = tid & 31, w = tid >> 5;
    const int wm = w & 1, wn = w >> 1;         // 2 x 8 warp grid
    const int mc = blockIdx.x & 3;
    const int nc0 = blockIdx.x >> 2;           // 0..147

    // stationary A chunk (fragment-order, verbatim copy)
    {
        const uint4* srcA = (const uint4*)(g_A + mc * 8192);
        for (int j = tid; j < 2048; j += 512)
            ((uint4*)sA)[j] = srcA[j];
    }
    // prologue: first B chunk into buffer 0
    {
        uint32_t* sB = sm1 + 8192;
        const uint4* src = (const uint4*)(g_XT + (size_t)nc0 * 16384u);
        for (int j = tid; j < 4096; j += 512)
            cpa16((uint32_t)__cvta_generic_to_shared(&sB[j * 4]), &src[j]);
        cpa_commit();
    }

    const int wn1 = wn & 1, brel = wn >> 1;
    const int ksbase = (mc * 2 + wm) * 4 + wn1 * 2;  // + p

    int it = 0;
    for (int nc = nc0; nc < 1024; nc += 148, ++it) {
        uint32_t* sB = sm1 + 8192 + (it & 1) * 16384;
        int ncn = nc + 148;
        if (ncn < 1024) {
            uint32_t* sBn = sm1 + 8192 + ((it + 1) & 1) * 16384;
            const uint4* src = (const uint4*)(g_XT + (size_t)ncn * 16384u);
            for (int j = tid; j < 4096; j += 512)
                cpa16((uint32_t)__cvta_generic_to_shared(&sBn[j * 4]), &src[j]);
            cpa_commit();
            cpa_wait1();
        } else {
            cpa_wait0();
        }
        __syncthreads();

        float acc[4][4][4];
#pragma unroll
        for (int a = 0; a < 4; ++a)
#pragma unroll
            for (int b = 0; b < 4; ++b)
#pragma unroll
                for (int q = 0; q < 4; ++q) acc[a][b][q] = 0.0f;

#pragma unroll
        for (int ks = 0; ks < 4; ++ks) {
            uint4 AH[4], AL[4], BQ[4];
#pragma unroll
            for (int mt = 0; mt < 4; ++mt) {
                int base = (((wm * 4 + mt) * 4 + ks) * 32 + lane) * 8;
                AH[mt] = *(const uint4*)&sA[base];
                AL[mt] = *(const uint4*)&sA[base + 4];
            }
#pragma unroll
            for (int nt = 0; nt < 4; ++nt)
                BQ[nt] = *(const uint4*)&sB[((ks * 32 + wn * 4 + nt) * 32 + lane) * 4];

            // term-major: hh, hl, lh -> dep distance 16
#pragma unroll
            for (int mt = 0; mt < 4; ++mt)
#pragma unroll
                for (int nt = 0; nt < 4; ++nt)
                    mma16816(acc[mt][nt], (const uint32_t*)&AH[mt],
                             (const uint32_t*)&BQ[nt]);
#pragma unroll
            for (int mt = 0; mt < 4; ++mt)
#pragma unroll
                for (int nt = 0; nt < 4; ++nt)
                    mma16816(acc[mt][nt], (const uint32_t*)&AH[mt],
                             ((const uint32_t*)&BQ[nt]) + 2);
#pragma unroll
            for (int mt = 0; mt < 4; ++mt)
#pragma unroll
                for (int nt = 0; nt < 4; ++nt)
                    mma16816(acc[mt][nt], (const uint32_t*)&AL[mt],
                             (const uint32_t*)&BQ[nt]);
        }

        // epilogue: fragment-order planes, fully coalesced STG.128.
        // Rb = (b0+brel)*4 + mt; ks2 = ksbase + p; word = {a0,a1,a2,a3}.
        const int b0 = nc * 4;
#pragma unroll
        for (int mt = 0; mt < 4; ++mt) {
            size_t RbBase = ((size_t)(b0 + brel) * 4 + mt) * 32;
#pragma unroll
            for (int p = 0; p < 2; ++p) {
                size_t idx = ((RbBase + ksbase + p) * 32 + lane) * 4;
                const float* A0 = acc[mt][2 * p];      // klo (j_k=0)
                const float* A1 = acc[mt][2 * p + 1];  // khi (j_k=1)
                uint4 vh, vl;
                vh.x = pack_plane(A0[0], A0[1], 0);  // a0: row o12,  klo
                vh.y = pack_plane(A0[2], A0[3], 0);  // a1: row o12+8,klo
                vh.z = pack_plane(A1[0], A1[1], 0);  // a2: row o12,  khi
                vh.w = pack_plane(A1[2], A1[3], 0);  // a3: row o12+8,khi
                vl.x = pack_plane(A0[0], A0[1], 1);
                vl.y = pack_plane(A0[2], A0[3], 1);
                vl.z = pack_plane(A1[0], A1[1], 1);
                vl.w = pack_plane(A1[2], A1[3], 1);
                *(uint4*)&g_Zh[idx] = vh;
                *(uint4*)&g_Zl[idx] = vl;
            }
        }
        __syncthreads();
    }
}

// ---------------------------------------------------------------------------
// k2 (stage 2): y = Z @ G23 + bias. 512 thr / 16 warps, CTA = 512 rows.
// A fragments: 4 coalesced LDG.128 per warp-ks from g_Z{h,l} (zero PRMT),
// 1-deep prefetch. B fragment-order in SMEM (LDS.128). Term-major MMA.
// ---------------------------------------------------------------------------
__global__ __launch_bounds__(512, 1) void k2(const float* __restrict__ bias,
                                             float* __restrict__ out) {
    extern __shared__ uint32_t sm2[];   // 32768 words = 128KB
    uint32_t* sB = sm2;
    const int tid = threadIdx.x;
    const int lane = tid & 31, w = tid >> 5;
    const int g = lane >> 2, t4 = lane & 3;

    {
        const uint4* src = (const uint4*)g_B;
        for (int j = tid; j < 8192; j += 512)
            ((uint4*)sB)[j] = src[j];
    }

    // A base: Rb = blockIdx.x*32 + w*2 + mt;  idx = ((Rb*32+ks)*32+lane)*4
    const size_t abase = (((size_t)blockIdx.x * 32 + w * 2) * 32 * 32 +
                          (size_t)lane) * 4;
    const uint32_t* ph = g_Zh + abase;
    const uint32_t* pl = g_Zl + abase;
    // mt stride = 32*32*4 = 4096 words; ks stride = 32*4 = 128 words

    float acc[2][8][4];
#pragma unroll
    for (int a = 0; a < 2; ++a)
#pragma unroll
        for (int b = 0; b < 8; ++b)
#pragma unroll
            for (int q = 0; q < 4; ++q) acc[a][b][q] = 0.0f;

    uint4 Ah[2][2], Al[2][2];   // [stage][mt]
#pragma unroll
    for (int mt = 0; mt < 2; ++mt) {
        Ah[0][mt] = *(const uint4*)(ph + mt * 4096);
        Al[0][mt] = *(const uint4*)(pl + mt * 4096);
    }
    __syncthreads();  // sB ready

    for (int ks = 0; ks < 32; ++ks) {
        const int cur = ks & 1;
        if (ks < 31) {  // prefetch next k-step's A fragments
            size_t off = (size_t)(ks + 1) * 128;
#pragma unroll
            for (int mt = 0; mt < 2; ++mt) {
                Ah[cur ^ 1][mt] = *(const uint4*)(ph + mt * 4096 + off);
                Al[cur ^ 1][mt] = *(const uint4*)(pl + mt * 4096 + off);
            }
        }
#pragma unroll
        for (int half = 0; half < 2; ++half) {
            uint4 BQ[4];
#pragma unroll
            for (int j = 0; j < 4; ++j) {
                int nb = half * 4 + j;
                BQ[j] = *(const uint4*)&sB[((ks * 8 + nb) * 32 + lane) * 4];
            }
            // term-major within half: dep distance 8
#pragma unroll
            for (int j = 0; j < 4; ++j)
#pragma unroll
                for (int mt = 0; mt < 2; ++mt)
                    mma16816(acc[mt][half * 4 + j], (const uint32_t*)&Ah[cur][mt],
                             (const uint32_t*)&BQ[j]);        // hh
#pragma unroll
            for (int j = 0; j < 4; ++j)
#pragma unroll
                for (int mt = 0; mt < 2; ++mt)
                    mma16816(acc[mt][half * 4 + j], (const uint32_t*)&Ah[cur][mt],
                             ((const uint32_t*)&BQ[j]) + 2);  // hl
#pragma unroll
            for (int j = 0; j < 4; ++j)
#pragma unroll
                for (int mt = 0; mt < 2; ++mt)
                    mma16816(acc[mt][half * 4 + j], (const uint32_t*)&Al[cur][mt],
                             (const uint32_t*)&BQ[j]);        // lh
        }
    }

    // epilogue: +bias, store
#pragma unroll
    for (int mt = 0; mt < 2; ++mt) {
        size_t grow0 = (size_t)blockIdx.x * 512 + w * 32 + mt * 16 + g;
#pragma unroll
        for (int half = 0; half < 2; ++half) {
            size_t grow = grow0 + half * 8;
            int o12 = (int)(grow & 63);
            float* orow = out + grow * 64;
            const int ci = half * 2;
#pragma unroll
            for (int nt = 0; nt < 8; ++nt) {
                int col = nt * 8 + t4 * 2;
                float2 bv = __ldg((const float2*)&bias[o12 * 64 + col]);
                float2 v;
                v.x = acc[mt][nt][ci] + bv.x;
                v.y = acc[mt][nt][ci + 1] + bv.y;
                *(float2*)&orow[col] = v;
            }
        }
    }
}

// ---------------------------------------------------------------------------
extern "C" void kernel_launch(void* const* d_in, const int* in_sizes, int n_in,
                              void* d_out, int out_size) {
    (void)in_sizes; (void)n_in; (void)out_size;
    const float* x    = (const float*)d_in[0];
    const float* c0   = (const float*)d_in[1];
    const float* c1   = (const float*)d_in[2];
    const float* c2   = (const float*)d_in[3];
    const float* c3   = (const float*)d_in[4];
    const float* bias = (const float*)d_in[5];
    float* out = (float*)d_out;

    cudaFuncSetAttribute(k1, cudaFuncAttributeMaxDynamicSharedMemorySize, 163840);
    cudaFuncSetAttribute(k2, cudaFuncAttributeMaxDynamicSharedMemorySize, 131072);

    k_prep<<<256, 256>>>(c0, c1, c2, c3);
    k_splitXT<<<4096, 256>>>(x);
    k1<<<592, 512, 163840>>>();            // coalesced fragment-order z stores
    k2<<<512, 512, 131072>>>(bias, out);   // coalesced LDG.128 A fragments
}

// round 13
// speedup vs baseline: 1.4243x; 1.2708x over previous
#include <cuda_runtime.h>
#include <cuda_bf16.h>
#include <cstdint>
#include <cstddef>

// ============================================================================
// TT-Linear as two merged GEMMs on HMMA (mma.sync bf16, baseline compute_103).
//
//   stage1: z[b][m̂=512][i34] = G01(512x64) @ x_b^T          (K=64)
//   stage2: y[(b,o12)][o34]  = ẑ_rows @ G23(512x64) + bias  (K=512)
//   3-term bf16 split per GEMM: Ah*Bh + Ah*Bl + Al*Bh.
//   G01 rows labeled m̂ = r2*64 + o12 so k1 accumulators ARE k2 A-fragments.
//
// R12 fix: k1's G01 prologue copied only 2048 uint4 (8K words) into the
// 32K-word sA — 3/4 of the stationary operand was uninitialized SMEM
// (garbage -> bf16 NaN -> NaN output). Loop scaled 4 -> 16 iterations.
// ============================================================================

//  g_A : [mrb=32][ks=4][lane=32][8 words: a0h,a1h,a2h,a3h,a0l,a1l,a2l,a3l]
//  g_B : [ks=32][nb=8][lane=32][4 words: b0h,b1h,b0l,b1l]
//  g_XT: [b=4096][ks=4][nb=8][lane=32][4 words]  (4096 words per row)
//  g_Z{h,l}: [Rb=16384][ks=32][lane=32][4 words {a0,a1,a2,a3}]
__device__ __align__(16) uint32_t g_A[32768];
__device__ __align__(16) uint32_t g_B[32768];
__device__ __align__(16) uint32_t g_XT[16777216u];
__device__ __align__(16) uint32_t g_Zh[67108864u];
__device__ __align__(16) uint32_t g_Zl[67108864u];

// ---------------------------------------------------------------- helpers
__device__ __forceinline__ uint32_t pack_plane(float a, float b, int plane) {
    __nv_bfloat16 ha = __float2bfloat16(a), hb = __float2bfloat16(b);
    if (plane == 0)
        return (uint32_t)__bfloat16_as_ushort(ha) |
               ((uint32_t)__bfloat16_as_ushort(hb) << 16);
    __nv_bfloat16 la = __float2bfloat16(a - __bfloat162float(ha));
    __nv_bfloat16 lb = __float2bfloat16(b - __bfloat162float(hb));
    return (uint32_t)__bfloat16_as_ushort(la) |
           ((uint32_t)__bfloat16_as_ushort(lb) << 16);
}
__device__ __forceinline__ void mma16816(float* c, const uint32_t* a,
                                         const uint32_t* b) {
    asm volatile(
        "mma.sync.aligned.m16n8k16.row.col.f32.bf16.bf16.f32 "
        "{%0,%1,%2,%3}, {%4,%5,%6,%7}, {%8,%9}, {%0,%1,%2,%3};"
        : "+f"(c[0]), "+f"(c[1]), "+f"(c[2]), "+f"(c[3])
        : "r"(a[0]), "r"(a[1]), "r"(a[2]), "r"(a[3]), "r"(b[0]), "r"(b[1]));
}
__device__ __forceinline__ uint32_t smaddr(const void* p) {
    return (uint32_t)__cvta_generic_to_shared(p);
}
__device__ __forceinline__ void cpa16(uint32_t dst_smem, const void* src) {
    asm volatile("cp.async.cg.shared.global [%0], [%1], 16;"
                 :: "r"(dst_smem), "l"(src) : "memory");
}
__device__ __forceinline__ void cpa_commit() {
    asm volatile("cp.async.commit_group;" ::: "memory");
}
__device__ __forceinline__ void cpa_wait0() {
    asm volatile("cp.async.wait_group 0;" ::: "memory");
}
__device__ __forceinline__ void cpa_wait1() {
    asm volatile("cp.async.wait_group 1;" ::: "memory");
}
__device__ __forceinline__ void cpa_wait2() {
    asm volatile("cp.async.wait_group 2;" ::: "memory");
}

// ---------------------------------------------------------------------------
// prep: merge core pairs into fragment-order hi/lo planes (m̂ = r2*64+o12).
// ---------------------------------------------------------------------------
__global__ void k_prep(const float* __restrict__ c0, const float* __restrict__ c1,
                       const float* __restrict__ c2, const float* __restrict__ c3) {
    int t = blockIdx.x * blockDim.x + threadIdx.x;  // 0..65535
    if (t < 32768) {
        int w = t & 7, lane = (t >> 3) & 31, ks = (t >> 8) & 3, mrb = t >> 10;
        int g = lane >> 2, t4 = lane & 3;
        int w2 = w & 3, plane = w >> 2;
        int mhat = mrb * 16 + (w2 & 1) * 8 + g;
        int k0 = ks * 16 + ((w2 >> 1) & 1) * 8 + t4 * 2;
        int r2 = mhat >> 6, o12 = mhat & 63;
        int o1 = o12 >> 3, o2 = o12 & 7;
        float s[2];
#pragma unroll
        for (int d = 0; d < 2; ++d) {
            int k = k0 + d;
            int i1 = k >> 3, i2 = k & 7;
            float acc = 0.0f;
#pragma unroll
            for (int r1 = 0; r1 < 8; ++r1)
                acc += c0[(i1 * 8 + o1) * 8 + r1] *
                       c1[((r1 * 8 + i2) * 8 + o2) * 8 + r2];
            s[d] = acc;
        }
        g_A[t] = pack_plane(s[0], s[1], plane);
    } else {
        int u = t - 32768;
        int w = u & 3, lane = (u >> 2) & 31, nb = (u >> 7) & 7, ks = u >> 10;
        int g = lane >> 2, t4 = lane & 3;
        int plane = w >> 1;
        int n  = nb * 8 + g;
        int k0 = ks * 16 + (w & 1) * 8 + t4 * 2;
        int o3 = n >> 3, o4 = n & 7;
        float s[2];
#pragma unroll
        for (int d = 0; d < 2; ++d) {
            int k2 = k0 + d;
            int r2 = k2 >> 6, i3 = (k2 >> 3) & 7, i4 = k2 & 7;
            float acc = 0.0f;
#pragma unroll
            for (int r3 = 0; r3 < 8; ++r3)
                acc += c2[((r2 * 8 + i3) * 8 + o3) * 8 + r3] *
                       c3[(r3 * 8 + i4) * 8 + o4];
            s[d] = acc;
        }
        g_B[u] = pack_plane(s[0], s[1], plane);
    }
}

// ---------------------------------------------------------------------------
// splitXT: x[b] fp32 -> per-row fragment-order planes:
//   g_XT[b*4096 + ks*1024 + nb*128 + lane*4 + w]
// ---------------------------------------------------------------------------
__global__ __launch_bounds__(256) void k_splitXT(const float* __restrict__ x) {
    __shared__ float sx[64 * 65];   // [i12][i34], pad 65
    const int tid = threadIdx.x;
    const int b = blockIdx.x;
    const float4* src = (const float4*)(x + (size_t)b * 4096);
#pragma unroll
    for (int p = 0; p < 4; ++p) {
        float4 v = src[tid + 256 * p];
        int j = tid + 256 * p;
        int i12 = j >> 4, c = (j & 15) * 4;
        float* d = &sx[i12 * 65 + c];
        d[0] = v.x; d[1] = v.y; d[2] = v.z; d[3] = v.w;
    }
    __syncthreads();
    uint32_t* dst = g_XT + (size_t)b * 4096;
#pragma unroll
    for (int it = 0; it < 16; ++it) {
        int widx = it * 256 + tid;  // = ks*1024 + nb*128 + lane*4 + w
        int w = widx & 3, lane = (widx >> 2) & 31;
        int nb = (widx >> 7) & 7, ks = widx >> 10;
        int g = lane >> 2, t4 = lane & 3;
        int plane = w >> 1;
        int i34 = nb * 8 + g;
        int k0 = ks * 16 + (w & 1) * 8 + t4 * 2;
        float f0 = sx[k0 * 65 + i34];
        float f1 = sx[(k0 + 1) * 65 + i34];
        dst[widx] = pack_plane(f0, f1, plane);
    }
}

// ---------------------------------------------------------------------------
// k1: z = G01 @ x_b^T, CTA tile 512m x 64n (one batch row per iter, 4 iters).
// G01 stationary in SMEM (cp.async, 128KB). x rows double-buffered (16KB).
// Warp w covers m̂ in [32w, 32w+32): warp tile 32m x 64n, 48 MMA per warp-ks.
// Epilogue: coalesced STG.128 into k2-fragment-order planes.
// ---------------------------------------------------------------------------
__global__ __launch_bounds__(512, 1) void k1() {
    extern __shared__ uint32_t sm1[];
    uint32_t* sA = sm1;              // 32768 words (G01 fragments, verbatim)
    uint32_t* sX = sm1 + 32768;      // 2 stages x 4096 words
    const int tid = threadIdx.x;
    const int lane = tid & 31, w = tid >> 5;
    const int b0 = blockIdx.x * 4;

    // prologue: G01 (group gA) — FULL 8192 uint4 (R12 fix: was p<4)
    {
        const uint4* srcA = (const uint4*)g_A;
#pragma unroll
        for (int p = 0; p < 16; ++p) {
            int j = tid + 512 * p;
            cpa16(smaddr(&sA[j * 4]), &srcA[j]);
        }
        cpa_commit();
    }
#pragma unroll
    for (int r = 0; r < 2; ++r) {
        const uint4* srcX = (const uint4*)(g_XT + (size_t)(b0 + r) * 4096);
#pragma unroll
        for (int p = 0; p < 2; ++p) {
            int j = tid + 512 * p;
            cpa16(smaddr(&sX[r * 4096 + j * 4]), &srcX[j]);
        }
        cpa_commit();
    }
    cpa_wait2();      // gA done
    __syncthreads();  // publish G01

    for (int r = 0; r < 4; ++r) {
        if (r < 3) cpa_wait1(); else cpa_wait0();  // row r done
        __syncthreads();                           // publish row r
        const uint32_t* sXs = sX + (r & 1) * 4096;

        float acc[2][8][4];
#pragma unroll
        for (int a = 0; a < 2; ++a)
#pragma unroll
            for (int b_ = 0; b_ < 8; ++b_)
#pragma unroll
                for (int q = 0; q < 4; ++q) acc[a][b_][q] = 0.0f;

#pragma unroll
        for (int ks = 0; ks < 4; ++ks) {
            uint4 AH[2], AL[2];
#pragma unroll
            for (int mt = 0; mt < 2; ++mt) {
                int base = (((w * 2 + mt) * 4 + ks) * 32 + lane) * 8;
                AH[mt] = *(const uint4*)&sA[base];
                AL[mt] = *(const uint4*)&sA[base + 4];
            }
#pragma unroll
            for (int half = 0; half < 2; ++half) {
                uint4 BQ[4];
#pragma unroll
                for (int j = 0; j < 4; ++j)
                    BQ[j] = *(const uint4*)&sXs[((ks * 8 + half * 4 + j) * 32 + lane) * 4];
#pragma unroll
                for (int j = 0; j < 4; ++j)
#pragma unroll
                    for (int mt = 0; mt < 2; ++mt)
                        mma16816(acc[mt][half * 4 + j], (const uint32_t*)&AH[mt],
                                 (const uint32_t*)&BQ[j]);        // hh
#pragma unroll
                for (int j = 0; j < 4; ++j)
#pragma unroll
                    for (int mt = 0; mt < 2; ++mt)
                        mma16816(acc[mt][half * 4 + j], (const uint32_t*)&AH[mt],
                                 ((const uint32_t*)&BQ[j]) + 2);  // hl
#pragma unroll
                for (int j = 0; j < 4; ++j)
#pragma unroll
                    for (int mt = 0; mt < 2; ++mt)
                        mma16816(acc[mt][half * 4 + j], (const uint32_t*)&AL[mt],
                                 (const uint32_t*)&BQ[j]);        // lh
            }
        }

        // epilogue: k2-fragment-order planes, coalesced STG.128
        const int b = b0 + r;
#pragma unroll
        for (int mt = 0; mt < 2; ++mt) {
            size_t Rb = (size_t)b * 4 + (w & 1) * 2 + mt;
#pragma unroll
            for (int np = 0; np < 4; ++np) {
                int ks2 = (w >> 1) * 4 + np;
                size_t idx = ((Rb * 32 + ks2) * 32 + lane) * 4;
                const float* A0 = acc[mt][2 * np];
                const float* A1 = acc[mt][2 * np + 1];
                uint4 vh, vl;
                vh.x = pack_plane(A0[0], A0[1], 0);
                vh.y = pack_plane(A0[2], A0[3], 0);
                vh.z = pack_plane(A1[0], A1[1], 0);
                vh.w = pack_plane(A1[2], A1[3], 0);
                vl.x = pack_plane(A0[0], A0[1], 1);
                vl.y = pack_plane(A0[2], A0[3], 1);
                vl.z = pack_plane(A1[0], A1[1], 1);
                vl.w = pack_plane(A1[2], A1[3], 1);
                *(uint4*)&g_Zh[idx] = vh;
                *(uint4*)&g_Zl[idx] = vl;
            }
        }
        __syncthreads();  // all reads of stage r&1 done
        if (r + 2 < 4) {  // prefetch row r+2 into the freed stage
            const uint4* srcX = (const uint4*)(g_XT + (size_t)(b0 + r + 2) * 4096);
#pragma unroll
            for (int p = 0; p < 2; ++p) {
                int j = tid + 512 * p;
                cpa16(smaddr(&sX[(r & 1) * 4096 + j * 4]), &srcX[j]);
            }
            cpa_commit();
        }
    }
}

// ---------------------------------------------------------------------------
// k2: y = ẑ @ G23 + bias. A streamed via per-thread cp.async SMEM ring
// (3 stages x 32KB, distance 2, no in-loop barriers). B resident (128KB).
// ---------------------------------------------------------------------------
__device__ __forceinline__ void k2_issueA(uint32_t* sA, int ks, int w,
                                          int lane, int bx) {
#pragma unroll
    for (int i = 0; i < 4; ++i) {
        int mt = i & 1, plane = i >> 1;
        size_t Rb = (size_t)bx * 32 + w * 2 + mt;
        const uint32_t* src = (plane ? g_Zl : g_Zh) +
                              ((Rb * 32 + (size_t)ks) * 32 + lane) * 4;
        cpa16(smaddr(&sA[(size_t)(ks % 3) * 8192 + ((w * 4 + i) * 32 + lane) * 4]),
              src);
    }
    cpa_commit();
}

__global__ __launch_bounds__(512, 1) void k2(const float* __restrict__ bias,
                                             float* __restrict__ out) {
    extern __shared__ uint32_t sm2[];
    uint32_t* sB = sm2;            // 32768 words
    uint32_t* sA = sm2 + 32768;    // 3 x 8192 words
    const int tid = threadIdx.x;
    const int lane = tid & 31, w = tid >> 5;
    const int g = lane >> 2, t4 = lane & 3;
    const int bx = blockIdx.x;

    // B via cp.async (group gB), then A stages 0,1
    {
        const uint4* src = (const uint4*)g_B;
#pragma unroll
        for (int p = 0; p < 16; ++p) {
            int j = tid + 512 * p;
            cpa16(smaddr(&sB[j * 4]), &src[j]);
        }
        cpa_commit();
    }
    k2_issueA(sA, 0, w, lane, bx);
    k2_issueA(sA, 1, w, lane, bx);
    cpa_wait2();      // gB done
    __syncthreads();  // publish B (A stages are per-thread private)

    float acc[2][8][4];
#pragma unroll
    for (int a = 0; a < 2; ++a)
#pragma unroll
        for (int b_ = 0; b_ < 8; ++b_)
#pragma unroll
            for (int q = 0; q < 4; ++q) acc[a][b_][q] = 0.0f;

    for (int ks = 0; ks < 32; ++ks) {
        if (ks < 31) cpa_wait1(); else cpa_wait0();  // stage ks ready (own)
        const uint32_t* sAs = sA + (size_t)(ks % 3) * 8192;
        uint4 Ah[2], Al[2];
        Ah[0] = *(const uint4*)&sAs[((w * 4 + 0) * 32 + lane) * 4];
        Ah[1] = *(const uint4*)&sAs[((w * 4 + 1) * 32 + lane) * 4];
        Al[0] = *(const uint4*)&sAs[((w * 4 + 2) * 32 + lane) * 4];
        Al[1] = *(const uint4*)&sAs[((w * 4 + 3) * 32 + lane) * 4];
        if (ks + 2 < 32) k2_issueA(sA, ks + 2, w, lane, bx);

#pragma unroll
        for (int half = 0; half < 2; ++half) {
            uint4 BQ[4];
#pragma unroll
            for (int j = 0; j < 4; ++j) {
                int nb = half * 4 + j;
                BQ[j] = *(const uint4*)&sB[((ks * 8 + nb) * 32 + lane) * 4];
            }
#pragma unroll
            for (int j = 0; j < 4; ++j)
#pragma unroll
                for (int mt = 0; mt < 2; ++mt)
                    mma16816(acc[mt][half * 4 + j], (const uint32_t*)&Ah[mt],
                             (const uint32_t*)&BQ[j]);        // hh
#pragma unroll
            for (int j = 0; j < 4; ++j)
#pragma unroll
                for (int mt = 0; mt < 2; ++mt)
                    mma16816(acc[mt][half * 4 + j], (const uint32_t*)&Ah[mt],
                             ((const uint32_t*)&BQ[j]) + 2);  // hl
#pragma unroll
            for (int j = 0; j < 4; ++j)
#pragma unroll
                for (int mt = 0; mt < 2; ++mt)
                    mma16816(acc[mt][half * 4 + j], (const uint32_t*)&Al[mt],
                             (const uint32_t*)&BQ[j]);        // lh
        }
    }

    // epilogue: +bias, store
#pragma unroll
    for (int mt = 0; mt < 2; ++mt) {
        size_t grow0 = (size_t)bx * 512 + w * 32 + mt * 16 + g;
#pragma unroll
        for (int half = 0; half < 2; ++half) {
            size_t grow = grow0 + half * 8;
            int o12 = (int)(grow & 63);
            float* orow = out + grow * 64;
            const int ci = half * 2;
#pragma unroll
            for (int nt = 0; nt < 8; ++nt) {
                int col = nt * 8 + t4 * 2;
                float2 bv = __ldg((const float2*)&bias[o12 * 64 + col]);
                float2 v;
                v.x = acc[mt][nt][ci] + bv.x;
                v.y = acc[mt][nt][ci + 1] + bv.y;
                *(float2*)&orow[col] = v;
            }
        }
    }
}

// ---------------------------------------------------------------------------
extern "C" void kernel_launch(void* const* d_in, const int* in_sizes, int n_in,
                              void* d_out, int out_size) {
    (void)in_sizes; (void)n_in; (void)out_size;
    const float* x    = (const float*)d_in[0];
    const float* c0   = (const float*)d_in[1];
    const float* c1   = (const float*)d_in[2];
    const float* c2   = (const float*)d_in[3];
    const float* c3   = (const float*)d_in[4];
    const float* bias = (const float*)d_in[5];
    float* out = (float*)d_out;

    cudaFuncSetAttribute(k1, cudaFuncAttributeMaxDynamicSharedMemorySize, 163840);
    cudaFuncSetAttribute(k2, cudaFuncAttributeMaxDynamicSharedMemorySize, 229376);

    k_prep<<<256, 256>>>(c0, c1, c2, c3);
    k_splitXT<<<4096, 256>>>(x);
    k1<<<1024, 512, 163840>>>();            // 4 batch rows per CTA, XT read once
    k2<<<512, 512, 229376>>>(bias, out);    // cp.async A-ring, distance 2
}

// round 14
// speedup vs baseline: 2.7979x; 1.9644x over previous
#include <cuda_runtime.h>
#include <cuda_fp16.h>
#include <cstdint>
#include <cstddef>

// ============================================================================
// TT-Linear as two merged GEMMs on HMMA, fp16 single-term (R13).
//
//   stage1: z[b][m̂=512][i34] = G01(512x64) @ x_b^T          (K=64)
//   stage2: y[(b,o12)][o34]  = ẑ_rows @ G23(512x64) + bias  (K=512)
//   G01 rows labeled m̂ = r2*64 + o12 so k1 accumulators ARE k2 A-fragments.
//
// R13 change: bf16 hi/lo 3-term -> fp16 1-term. fp16's 11 mantissa bits give
// norm rel_err ~3e-4 (< 1e-3 with 3.3x margin); MMA count drops 3x (25.2M ->
// 8.4M), z traffic halves (268MB), cp.async count halves. All fragment
// layouts collapse to single-plane; B-fragments pack 2 nb per LDS.128.
// ============================================================================

//  g_A : [mrb=32][ks=4][lane=32][4 words: a0,a1,a2,a3]           (fp16x2 words)
//  g_B : [ks=32][nbp=4][lane=32][4 words: nb0{b0,b1}, nb1{b0,b1}]
//  g_XT: [b=4096][ks=4][nbp=4][lane=32][4 words]  (2048 words per row)
//  g_Z : [Rb=16384][ks2=32][lane=32][4 words {a0,a1,a2,a3}]
__device__ __align__(16) uint32_t g_A[16384];
__device__ __align__(16) uint32_t g_B[16384];
__device__ __align__(16) uint32_t g_XT[8388608u];
__device__ __align__(16) uint32_t g_Z[67108864u];

// ---------------------------------------------------------------- helpers
__device__ __forceinline__ uint32_t pack_h2(float a, float b) {
    // low half = a, high half = b
    uint32_t r;
    asm("cvt.rn.f16x2.f32 %0, %1, %2;" : "=r"(r) : "f"(b), "f"(a));
    return r;
}
__device__ __forceinline__ void mma16816(float* c, const uint32_t* a,
                                         const uint32_t* b) {
    asm volatile(
        "mma.sync.aligned.m16n8k16.row.col.f32.f16.f16.f32 "
        "{%0,%1,%2,%3}, {%4,%5,%6,%7}, {%8,%9}, {%0,%1,%2,%3};"
        : "+f"(c[0]), "+f"(c[1]), "+f"(c[2]), "+f"(c[3])
        : "r"(a[0]), "r"(a[1]), "r"(a[2]), "r"(a[3]), "r"(b[0]), "r"(b[1]));
}
__device__ __forceinline__ uint32_t smaddr(const void* p) {
    return (uint32_t)__cvta_generic_to_shared(p);
}
__device__ __forceinline__ void cpa16(uint32_t dst_smem, const void* src) {
    asm volatile("cp.async.cg.shared.global [%0], [%1], 16;"
                 :: "r"(dst_smem), "l"(src) : "memory");
}
__device__ __forceinline__ void cpa_commit() {
    asm volatile("cp.async.commit_group;" ::: "memory");
}
__device__ __forceinline__ void cpa_wait0() {
    asm volatile("cp.async.wait_group 0;" ::: "memory");
}
__device__ __forceinline__ void cpa_wait1() {
    asm volatile("cp.async.wait_group 1;" ::: "memory");
}
__device__ __forceinline__ void cpa_wait2() {
    asm volatile("cp.async.wait_group 2;" ::: "memory");
}
__device__ __forceinline__ void cpa_wait3() {
    asm volatile("cp.async.wait_group 3;" ::: "memory");
}

// ---------------------------------------------------------------------------
// prep: merge core pairs into fp16 fragment-order words (m̂ = r2*64+o12).
// ---------------------------------------------------------------------------
__global__ void k_prep(const float* __restrict__ c0, const float* __restrict__ c1,
                       const float* __restrict__ c2, const float* __restrict__ c3) {
    int t = blockIdx.x * blockDim.x + threadIdx.x;  // 0..32767
    if (t < 16384) {
        // g_A word t = ((mrb*4+ks)*32+lane)*4 + w2
        int w2 = t & 3, lane = (t >> 2) & 31, ks = (t >> 7) & 3, mrb = t >> 9;
        int g = lane >> 2, t4 = lane & 3;
        int mhat = mrb * 16 + (w2 & 1) * 8 + g;
        int k0 = ks * 16 + ((w2 >> 1) & 1) * 8 + t4 * 2;
        int r2 = mhat >> 6, o12 = mhat & 63;
        int o1 = o12 >> 3, o2 = o12 & 7;
        float s[2];
#pragma unroll
        for (int d = 0; d < 2; ++d) {
            int k = k0 + d;
            int i1 = k >> 3, i2 = k & 7;
            float acc = 0.0f;
#pragma unroll
            for (int r1 = 0; r1 < 8; ++r1)
                acc += c0[(i1 * 8 + o1) * 8 + r1] *
                       c1[((r1 * 8 + i2) * 8 + o2) * 8 + r2];
            s[d] = acc;
        }
        g_A[t] = pack_h2(s[0], s[1]);
    } else {
        // g_B word u = ((ks*4+nbp)*32+lane)*4 + w
        int u = t - 16384;
        int w = u & 3, lane = (u >> 2) & 31, nbp = (u >> 7) & 3, ks = u >> 9;
        int g = lane >> 2, t4 = lane & 3;
        int nb = nbp * 2 + (w >> 1);
        int n  = nb * 8 + g;
        int k0 = ks * 16 + (w & 1) * 8 + t4 * 2;
        int o3 = n >> 3, o4 = n & 7;
        float s[2];
#pragma unroll
        for (int d = 0; d < 2; ++d) {
            int k2v = k0 + d;
            int r2 = k2v >> 6, i3 = (k2v >> 3) & 7, i4 = k2v & 7;
            float acc = 0.0f;
#pragma unroll
            for (int r3 = 0; r3 < 8; ++r3)
                acc += c2[((r2 * 8 + i3) * 8 + o3) * 8 + r3] *
                       c3[(r3 * 8 + i4) * 8 + o4];
            s[d] = acc;
        }
        g_B[u] = pack_h2(s[0], s[1]);
    }
}

// ---------------------------------------------------------------------------
// splitXT: x[b] fp32 -> fp16 fragment-order words (2048 per row):
//   g_XT[b*2048 + ks*512 + nbp*128 + lane*4 + w]
// ---------------------------------------------------------------------------
__global__ __launch_bounds__(256) void k_splitXT(const float* __restrict__ x) {
    __shared__ float sx[64 * 65];   // [i12][i34], pad 65
    const int tid = threadIdx.x;
    const int b = blockIdx.x;
    const float4* src = (const float4*)(x + (size_t)b * 4096);
#pragma unroll
    for (int p = 0; p < 4; ++p) {
        float4 v = src[tid + 256 * p];
        int j = tid + 256 * p;
        int i12 = j >> 4, c = (j & 15) * 4;
        float* d = &sx[i12 * 65 + c];
        d[0] = v.x; d[1] = v.y; d[2] = v.z; d[3] = v.w;
    }
    __syncthreads();
    uint32_t* dst = g_XT + (size_t)b * 2048;
#pragma unroll
    for (int it = 0; it < 8; ++it) {
        int widx = it * 256 + tid;  // [ks=4][nbp=4][lane=32][w=4]
        int w = widx & 3, lane = (widx >> 2) & 31;
        int nbp = (widx >> 7) & 3, ks = widx >> 9;
        int g = lane >> 2, t4 = lane & 3;
        int nb = nbp * 2 + (w >> 1);
        int i34 = nb * 8 + g;
        int k0 = ks * 16 + (w & 1) * 8 + t4 * 2;
        dst[widx] = pack_h2(sx[k0 * 65 + i34], sx[(k0 + 1) * 65 + i34]);
    }
}

// ---------------------------------------------------------------------------
// k1: z = G01 @ x_b^T, CTA tile 512m x 64n (one batch row per iter, 4 iters).
// G01 stationary in SMEM (64KB). x rows double-buffered (8KB each).
// Warp w covers m̂ in [32w, 32w+32). 64 MMAs per warp per row.
// Epilogue: coalesced STG.128 into k2-fragment-order g_Z.
// ---------------------------------------------------------------------------
__global__ __launch_bounds__(512, 1) void k1() {
    extern __shared__ uint32_t sm1[];
    uint32_t* sA = sm1;              // 16384 words (G01 fragments, verbatim)
    uint32_t* sX = sm1 + 16384;      // 2 stages x 2048 words
    const int tid = threadIdx.x;
    const int lane = tid & 31, w = tid >> 5;
    const int b0 = blockIdx.x * 4;

    // prologue: G01 (group gA), x rows 0,1
    {
        const uint4* srcA = (const uint4*)g_A;
#pragma unroll
        for (int p = 0; p < 8; ++p) {
            int j = tid + 512 * p;
            cpa16(smaddr(&sA[j * 4]), &srcA[j]);
        }
        cpa_commit();
    }
#pragma unroll
    for (int r = 0; r < 2; ++r) {
        const uint4* srcX = (const uint4*)(g_XT + (size_t)(b0 + r) * 2048);
        cpa16(smaddr(&sX[r * 2048 + tid * 4]), &srcX[tid]);
        cpa_commit();
    }
    cpa_wait2();      // gA done
    __syncthreads();  // publish G01

    for (int r = 0; r < 4; ++r) {
        if (r < 3) cpa_wait1(); else cpa_wait0();  // row r done
        __syncthreads();                           // publish row r
        const uint32_t* sXs = sX + (r & 1) * 2048;

        float acc[2][8][4];
#pragma unroll
        for (int a = 0; a < 2; ++a)
#pragma unroll
            for (int b_ = 0; b_ < 8; ++b_)
#pragma unroll
                for (int q = 0; q < 4; ++q) acc[a][b_][q] = 0.0f;

#pragma unroll
        for (int ks = 0; ks < 4; ++ks) {
            uint4 AQ[2];
#pragma unroll
            for (int mt = 0; mt < 2; ++mt)
                AQ[mt] = *(const uint4*)&sA[(((w * 2 + mt) * 4 + ks) * 32 + lane) * 4];
#pragma unroll
            for (int nbp = 0; nbp < 4; ++nbp) {
                uint4 BQ = *(const uint4*)&sXs[((ks * 4 + nbp) * 32 + lane) * 4];
#pragma unroll
                for (int mt = 0; mt < 2; ++mt) {
                    mma16816(acc[mt][2 * nbp],     (const uint32_t*)&AQ[mt], &BQ.x);
                    mma16816(acc[mt][2 * nbp + 1], (const uint32_t*)&AQ[mt], &BQ.z);
                }
            }
        }

        // epilogue: k2-fragment-order, coalesced STG.128
        const int b = b0 + r;
#pragma unroll
        for (int mt = 0; mt < 2; ++mt) {
            size_t Rb = (size_t)b * 4 + (w & 1) * 2 + mt;
#pragma unroll
            for (int np = 0; np < 4; ++np) {
                int ks2 = (w >> 1) * 4 + np;
                size_t idx = ((Rb * 32 + ks2) * 32 + lane) * 4;
                const float* A0 = acc[mt][2 * np];
                const float* A1 = acc[mt][2 * np + 1];
                uint4 v;
                v.x = pack_h2(A0[0], A0[1]);   // a0: row g,   k-lo
                v.y = pack_h2(A0[2], A0[3]);   // a1: row g+8, k-lo
                v.z = pack_h2(A1[0], A1[1]);   // a2: row g,   k-hi
                v.w = pack_h2(A1[2], A1[3]);   // a3: row g+8, k-hi
                *(uint4*)&g_Z[idx] = v;
            }
        }
        __syncthreads();  // all reads of stage r&1 done
        if (r + 2 < 4) {  // prefetch row r+2 into the freed stage
            const uint4* srcX = (const uint4*)(g_XT + (size_t)(b0 + r + 2) * 2048);
            cpa16(smaddr(&sX[(r & 1) * 2048 + tid * 4]), &srcX[tid]);
            cpa_commit();
        }
    }
}

// ---------------------------------------------------------------------------
// k2: y = ẑ @ G23 + bias. A via per-thread cp.async SMEM ring (4 stages x
// 16KB, distance 3, no in-loop barriers). B resident (64KB).
// ---------------------------------------------------------------------------
__device__ __forceinline__ void k2_issueA(uint32_t* sA, int ks, int w,
                                          int lane, int bx) {
#pragma unroll
    for (int mt = 0; mt < 2; ++mt) {
        size_t Rb = (size_t)bx * 32 + w * 2 + mt;
        const uint32_t* src = g_Z + ((Rb * 32 + (size_t)ks) * 32 + lane) * 4;
        cpa16(smaddr(&sA[(size_t)(ks & 3) * 4096 + ((w * 2 + mt) * 32 + lane) * 4]),
              src);
    }
    cpa_commit();
}

__global__ __launch_bounds__(512, 1) void k2(const float* __restrict__ bias,
                                             float* __restrict__ out) {
    extern __shared__ uint32_t sm2[];
    uint32_t* sB = sm2;            // 16384 words
    uint32_t* sA = sm2 + 16384;    // 4 x 4096 words
    const int tid = threadIdx.x;
    const int lane = tid & 31, w = tid >> 5;
    const int g = lane >> 2, t4 = lane & 3;
    const int bx = blockIdx.x;

    // B via cp.async (group gB), then A stages 0,1,2
    {
        const uint4* src = (const uint4*)g_B;
#pragma unroll
        for (int p = 0; p < 8; ++p) {
            int j = tid + 512 * p;
            cpa16(smaddr(&sB[j * 4]), &src[j]);
        }
        cpa_commit();
    }
    k2_issueA(sA, 0, w, lane, bx);
    k2_issueA(sA, 1, w, lane, bx);
    k2_issueA(sA, 2, w, lane, bx);
    cpa_wait3();      // gB done
    __syncthreads();  // publish B (A stages are per-thread private)

    float acc[2][8][4];
#pragma unroll
    for (int a = 0; a < 2; ++a)
#pragma unroll
        for (int b_ = 0; b_ < 8; ++b_)
#pragma unroll
            for (int q = 0; q < 4; ++q) acc[a][b_][q] = 0.0f;

    for (int ks = 0; ks < 32; ++ks) {
        if (ks < 30) cpa_wait2();
        else if (ks == 30) cpa_wait1();
        else cpa_wait0();
        const uint32_t* sAs = sA + (size_t)(ks & 3) * 4096;
        uint4 Ah[2];
        Ah[0] = *(const uint4*)&sAs[((w * 2 + 0) * 32 + lane) * 4];
        Ah[1] = *(const uint4*)&sAs[((w * 2 + 1) * 32 + lane) * 4];
        if (ks + 3 < 32) k2_issueA(sA, ks + 3, w, lane, bx);

#pragma unroll
        for (int nbp = 0; nbp < 4; ++nbp) {
            uint4 BQ = *(const uint4*)&sB[((ks * 4 + nbp) * 32 + lane) * 4];
#pragma unroll
            for (int mt = 0; mt < 2; ++mt) {
                mma16816(acc[mt][2 * nbp],     (const uint32_t*)&Ah[mt], &BQ.x);
                mma16816(acc[mt][2 * nbp + 1], (const uint32_t*)&Ah[mt], &BQ.z);
            }
        }
    }

    // epilogue: +bias, store
#pragma unroll
    for (int mt = 0; mt < 2; ++mt) {
        size_t grow0 = (size_t)bx * 512 + w * 32 + mt * 16 + g;
#pragma unroll
        for (int half = 0; half < 2; ++half) {
            size_t grow = grow0 + half * 8;
            int o12 = (int)(grow & 63);
            float* orow = out + grow * 64;
            const int ci = half * 2;
#pragma unroll
            for (int nt = 0; nt < 8; ++nt) {
                int col = nt * 8 + t4 * 2;
                float2 bv = __ldg((const float2*)&bias[o12 * 64 + col]);
                float2 v;
                v.x = acc[mt][nt][ci] + bv.x;
                v.y = acc[mt][nt][ci + 1] + bv.y;
                *(float2*)&orow[col] = v;
            }
        }
    }
}

// ---------------------------------------------------------------------------
extern "C" void kernel_launch(void* const* d_in, const int* in_sizes, int n_in,
                              void* d_out, int out_size) {
    (void)in_sizes; (void)n_in; (void)out_size;
    const float* x    = (const float*)d_in[0];
    const float* c0   = (const float*)d_in[1];
    const float* c1   = (const float*)d_in[2];
    const float* c2   = (const float*)d_in[3];
    const float* c3   = (const float*)d_in[4];
    const float* bias = (const float*)d_in[5];
    float* out = (float*)d_out;

    cudaFuncSetAttribute(k1, cudaFuncAttributeMaxDynamicSharedMemorySize, 81920);
    cudaFuncSetAttribute(k2, cudaFuncAttributeMaxDynamicSharedMemorySize, 131072);

    k_prep<<<128, 256>>>(c0, c1, c2, c3);
    k_splitXT<<<4096, 256>>>(x);
    k1<<<1024, 512, 81920>>>();            // fp16 1-term, 4 rows per CTA
    k2<<<512, 512, 131072>>>(bias, out);   // fp16 1-term, 4-stage A ring
}

// round 15
// speedup vs baseline: 3.1288x; 1.1183x over previous
#include <cuda_runtime.h>
#include <cuda_fp16.h>
#include <cstdint>
#include <cstddef>

// ============================================================================
// TT-Linear, fp16 HMMA, FUSED two-stage GEMM (R14): z never touches DRAM.
//
//   stage1: z_b[m̂=512][i34=64] = G01(512x64) @ x_b^T   (K=64)   -> SMEM
//   stage2: y_b[o12=64][o34=64] = ẑ_b @ G23(512x64) + bias (K=512)
//   m̂ = r2*64 + o12, so stage1 accumulators ARE stage2 A-fragments
//   (layouts identical to the R13 k1-epilogue / k2-A-read pair that passed).
//
// SMEM per CTA: G01 64K + G23 64K + z 64K + x 2x8K = 208KB. One CTA = 4 rows.
// DRAM traffic drops from ~640MB to ~100MB (XT in, y out).
// ============================================================================

//  g_A : [mrb=32][ks=4][lane=32][4 words: a0,a1,a2,a3]           (fp16x2)
//  g_B : [ks=32][nbp=4][lane=32][4 words: nb0{b0,b1}, nb1{b0,b1}]
//  g_XT: [b=4096][ks=4][nbp=4][lane=32][4 words]  (2048 words per row)
__device__ __align__(16) uint32_t g_A[16384];
__device__ __align__(16) uint32_t g_B[16384];
__device__ __align__(16) uint32_t g_XT[8388608u];

// ---------------------------------------------------------------- helpers
__device__ __forceinline__ uint32_t pack_h2(float a, float b) {
    uint32_t r;
    asm("cvt.rn.f16x2.f32 %0, %1, %2;" : "=r"(r) : "f"(b), "f"(a));
    return r;
}
__device__ __forceinline__ void mma16816(float* c, const uint32_t* a,
                                         const uint32_t* b) {
    asm volatile(
        "mma.sync.aligned.m16n8k16.row.col.f32.f16.f16.f32 "
        "{%0,%1,%2,%3}, {%4,%5,%6,%7}, {%8,%9}, {%0,%1,%2,%3};"
        : "+f"(c[0]), "+f"(c[1]), "+f"(c[2]), "+f"(c[3])
        : "r"(a[0]), "r"(a[1]), "r"(a[2]), "r"(a[3]), "r"(b[0]), "r"(b[1]));
}
__device__ __forceinline__ uint32_t smaddr(const void* p) {
    return (uint32_t)__cvta_generic_to_shared(p);
}
__device__ __forceinline__ void cpa16(uint32_t dst_smem, const void* src) {
    asm volatile("cp.async.cg.shared.global [%0], [%1], 16;"
                 :: "r"(dst_smem), "l"(src) : "memory");
}
__device__ __forceinline__ void cpa_commit() {
    asm volatile("cp.async.commit_group;" ::: "memory");
}
__device__ __forceinline__ void cpa_wait0() {
    asm volatile("cp.async.wait_group 0;" ::: "memory");
}
__device__ __forceinline__ void cpa_wait1() {
    asm volatile("cp.async.wait_group 1;" ::: "memory");
}

// ---------------------------------------------------------------------------
// prep: merge core pairs into fp16 fragment-order words (m̂ = r2*64+o12).
// ---------------------------------------------------------------------------
__global__ void k_prep(const float* __restrict__ c0, const float* __restrict__ c1,
                       const float* __restrict__ c2, const float* __restrict__ c3) {
    int t = blockIdx.x * blockDim.x + threadIdx.x;  // 0..32767
    if (t < 16384) {
        int w2 = t & 3, lane = (t >> 2) & 31, ks = (t >> 7) & 3, mrb = t >> 9;
        int g = lane >> 2, t4 = lane & 3;
        int mhat = mrb * 16 + (w2 & 1) * 8 + g;
        int k0 = ks * 16 + ((w2 >> 1) & 1) * 8 + t4 * 2;
        int r2 = mhat >> 6, o12 = mhat & 63;
        int o1 = o12 >> 3, o2 = o12 & 7;
        float s[2];
#pragma unroll
        for (int d = 0; d < 2; ++d) {
            int k = k0 + d;
            int i1 = k >> 3, i2 = k & 7;
            float acc = 0.0f;
#pragma unroll
            for (int r1 = 0; r1 < 8; ++r1)
                acc += c0[(i1 * 8 + o1) * 8 + r1] *
                       c1[((r1 * 8 + i2) * 8 + o2) * 8 + r2];
            s[d] = acc;
        }
        g_A[t] = pack_h2(s[0], s[1]);
    } else {
        int u = t - 16384;
        int w = u & 3, lane = (u >> 2) & 31, nbp = (u >> 7) & 3, ks = u >> 9;
        int g = lane >> 2, t4 = lane & 3;
        int nb = nbp * 2 + (w >> 1);
        int n  = nb * 8 + g;
        int k0 = ks * 16 + (w & 1) * 8 + t4 * 2;
        int o3 = n >> 3, o4 = n & 7;
        float s[2];
#pragma unroll
        for (int d = 0; d < 2; ++d) {
            int k2v = k0 + d;
            int r2 = k2v >> 6, i3 = (k2v >> 3) & 7, i4 = k2v & 7;
            float acc = 0.0f;
#pragma unroll
            for (int r3 = 0; r3 < 8; ++r3)
                acc += c2[((r2 * 8 + i3) * 8 + o3) * 8 + r3] *
                       c3[(r3 * 8 + i4) * 8 + o4];
            s[d] = acc;
        }
        g_B[u] = pack_h2(s[0], s[1]);
    }
}

// ---------------------------------------------------------------------------
// splitXT: x[b] fp32 -> fp16 fragment-order words (2048 per row).
// ---------------------------------------------------------------------------
__global__ __launch_bounds__(256) void k_splitXT(const float* __restrict__ x) {
    __shared__ float sx[64 * 65];
    const int tid = threadIdx.x;
    const int b = blockIdx.x;
    const float4* src = (const float4*)(x + (size_t)b * 4096);
#pragma unroll
    for (int p = 0; p < 4; ++p) {
        float4 v = src[tid + 256 * p];
        int j = tid + 256 * p;
        int i12 = j >> 4, c = (j & 15) * 4;
        float* d = &sx[i12 * 65 + c];
        d[0] = v.x; d[1] = v.y; d[2] = v.z; d[3] = v.w;
    }
    __syncthreads();
    uint32_t* dst = g_XT + (size_t)b * 2048;
#pragma unroll
    for (int it = 0; it < 8; ++it) {
        int widx = it * 256 + tid;
        int w = widx & 3, lane = (widx >> 2) & 31;
        int nbp = (widx >> 7) & 3, ks = widx >> 9;
        int g = lane >> 2, t4 = lane & 3;
        int nb = nbp * 2 + (w >> 1);
        int i34 = nb * 8 + g;
        int k0 = ks * 16 + (w & 1) * 8 + t4 * 2;
        dst[widx] = pack_h2(sx[k0 * 65 + i34], sx[(k0 + 1) * 65 + i34]);
    }
}

// ---------------------------------------------------------------------------
// fused: 4 batch rows per CTA; per row stage1 -> SMEM z -> stage2 -> out.
// ---------------------------------------------------------------------------
__global__ __launch_bounds__(512, 1) void k_fused(const float* __restrict__ bias,
                                                  float* __restrict__ out) {
    extern __shared__ uint32_t sm[];
    uint32_t* sG01 = sm;             // 16384 words
    uint32_t* sG23 = sm + 16384;     // 16384 words
    uint32_t* sZ   = sm + 32768;     // 16384 words
    uint32_t* sX   = sm + 49152;     // 2 stages x 2048 words
    const int tid = threadIdx.x;
    const int lane = tid & 31, w = tid >> 5;
    const int g = lane >> 2, t4 = lane & 3;
    const int b0 = blockIdx.x * 4;

    // group g0: G01 + x row b0   (needed for stage1 of row 0)
    {
        const uint4* srcA = (const uint4*)g_A;
#pragma unroll
        for (int p = 0; p < 8; ++p) {
            int j = tid + 512 * p;
            cpa16(smaddr(&sG01[j * 4]), &srcA[j]);
        }
        const uint4* sx0 = (const uint4*)(g_XT + (size_t)b0 * 2048);
        cpa16(smaddr(&sX[tid * 4]), &sx0[tid]);
        cpa_commit();
    }
    // group g1: G23 + x row b0+1 (needed for stage2 of row 0 / stage1 of row 1)
    {
        const uint4* srcB = (const uint4*)g_B;
#pragma unroll
        for (int p = 0; p < 8; ++p) {
            int j = tid + 512 * p;
            cpa16(smaddr(&sG23[j * 4]), &srcB[j]);
        }
        const uint4* sx1 = (const uint4*)(g_XT + (size_t)(b0 + 1) * 2048);
        cpa16(smaddr(&sX[2048 + tid * 4]), &sx1[tid]);
        cpa_commit();
    }

    const int mt2 = w >> 2, nbp2 = w & 3;  // stage2 warp mapping

    for (int r = 0; r < 4; ++r) {
        if (r == 0 || r == 2) cpa_wait1();
        else if (r == 3) cpa_wait0();
        __syncthreads();   // (a) publish x[r]; sZ free of stage2(r-1) readers
        const uint32_t* sXs = sX + (r & 1) * 2048;

        // ---------------- stage 1: z = G01 @ x_r^T ----------------
        float acc1[2][8][4];
#pragma unroll
        for (int a = 0; a < 2; ++a)
#pragma unroll
            for (int b_ = 0; b_ < 8; ++b_)
#pragma unroll
                for (int q = 0; q < 4; ++q) acc1[a][b_][q] = 0.0f;

#pragma unroll
        for (int ks = 0; ks < 4; ++ks) {
            uint4 AQ[2];
#pragma unroll
            for (int mt = 0; mt < 2; ++mt)
                AQ[mt] = *(const uint4*)&sG01[(((w * 2 + mt) * 4 + ks) * 32 + lane) * 4];
#pragma unroll
            for (int nbp = 0; nbp < 4; ++nbp) {
                uint4 BQ = *(const uint4*)&sXs[((ks * 4 + nbp) * 32 + lane) * 4];
#pragma unroll
                for (int mt = 0; mt < 2; ++mt) {
                    mma16816(acc1[mt][2 * nbp],     (const uint32_t*)&AQ[mt], &BQ.x);
                    mma16816(acc1[mt][2 * nbp + 1], (const uint32_t*)&AQ[mt], &BQ.z);
                }
            }
        }
        // STS z fragments (R13 k1-epilogue layout, Rb local)
#pragma unroll
        for (int mt = 0; mt < 2; ++mt) {
            int Rb_rel = (w & 1) * 2 + mt;
#pragma unroll
            for (int np = 0; np < 4; ++np) {
                int ks2 = (w >> 1) * 4 + np;
                uint32_t idx = (uint32_t)((Rb_rel * 32 + ks2) * 32 + lane) * 4;
                const float* A0 = acc1[mt][2 * np];
                const float* A1 = acc1[mt][2 * np + 1];
                uint4 v;
                v.x = pack_h2(A0[0], A0[1]);
                v.y = pack_h2(A0[2], A0[3]);
                v.z = pack_h2(A1[0], A1[1]);
                v.w = pack_h2(A1[2], A1[3]);
                *(uint4*)&sZ[idx] = v;
            }
        }
        if (r == 0) cpa_wait0();   // G23 (+x1) complete before stage2(0)
        __syncthreads();           // (b) publish sZ (and sG23 at r==0)

        // ---------------- stage 2: y_r = ẑ @ G23 + bias ----------------
        float acc2[2][4];
#pragma unroll
        for (int j = 0; j < 2; ++j)
#pragma unroll
            for (int q = 0; q < 4; ++q) acc2[j][q] = 0.0f;

#pragma unroll 8
        for (int ks = 0; ks < 32; ++ks) {
            uint4 AQ = *(const uint4*)&sZ[((mt2 * 32 + ks) * 32 + lane) * 4];
            uint4 BQ = *(const uint4*)&sG23[((ks * 4 + nbp2) * 32 + lane) * 4];
            mma16816(acc2[0], (const uint32_t*)&AQ, &BQ.x);
            mma16816(acc2[1], (const uint32_t*)&AQ, &BQ.z);
        }

        const int b = b0 + r;
#pragma unroll
        for (int j = 0; j < 2; ++j) {
            int nb = nbp2 * 2 + j;
            int col = nb * 8 + t4 * 2;
            int o12a = mt2 * 16 + g;
            float2 bva = __ldg((const float2*)&bias[o12a * 64 + col]);
            float2 va;
            va.x = acc2[j][0] + bva.x;
            va.y = acc2[j][1] + bva.y;
            *(float2*)&out[((size_t)b * 64 + o12a) * 64 + col] = va;
            int o12b = o12a + 8;
            float2 bvb = __ldg((const float2*)&bias[o12b * 64 + col]);
            float2 vb;
            vb.x = acc2[j][2] + bvb.x;
            vb.y = acc2[j][3] + bvb.y;
            *(float2*)&out[((size_t)b * 64 + o12b) * 64 + col] = vb;
        }

        if (r < 2) {  // prefetch x row r+2 into the buffer stage1(r) just freed
            const uint4* srcX = (const uint4*)(g_XT + (size_t)(b0 + r + 2) * 2048);
            cpa16(smaddr(&sX[(r & 1) * 2048 + tid * 4]), &srcX[tid]);
            cpa_commit();
        }
    }
}

// ---------------------------------------------------------------------------
extern "C" void kernel_launch(void* const* d_in, const int* in_sizes, int n_in,
                              void* d_out, int out_size) {
    (void)in_sizes; (void)n_in; (void)out_size;
    const float* x    = (const float*)d_in[0];
    const float* c0   = (const float*)d_in[1];
    const float* c1   = (const float*)d_in[2];
    const float* c2   = (const float*)d_in[3];
    const float* c3   = (const float*)d_in[4];
    const float* bias = (const float*)d_in[5];
    float* out = (float*)d_out;

    cudaFuncSetAttribute(k_fused, cudaFuncAttributeMaxDynamicSharedMemorySize,
                         212992);

    k_prep<<<128, 256>>>(c0, c1, c2, c3);
    k_splitXT<<<4096, 256>>>(x);
    k_fused<<<1024, 512, 212992>>>(bias, out);  // z lives in SMEM only
}